// round 5
// baseline (speedup 1.0000x reference)
#include <cuda_runtime.h>
#include <math.h>

// Problem constants (fixed by setup_inputs)
#define BB 64
#define LL 512
#define NNCH 64
#define AAA 64
#define DDD 256
#define PPP 16

// Scratch (no cudaMalloc allowed). conv partials: [b][slab(8)][o(32)]
__device__ float g_partial[BB * 8 * 32];

// -------- packed fp32x2 FMA (Blackwell FFMA2) --------
__device__ __forceinline__ void fma2(unsigned long long& c, unsigned long long a,
                                     unsigned long long b) {
    asm("fma.rn.f32x2 %0, %1, %2, %0;" : "+l"(c) : "l"(a), "l"(b));
}
__device__ __forceinline__ ulonglong2 as_ull2(float4 v) {
    return *reinterpret_cast<ulonglong2*>(&v);
}
__device__ __forceinline__ float2 as_f2(unsigned long long v) {
    return *reinterpret_cast<float2*>(&v);
}
__device__ __forceinline__ unsigned long long dup2(float s) {
    float2 t = make_float2(s, s);
    return *reinterpret_cast<unsigned long long*>(&t);
}

// ============================================================================
// Kernel 1: Conv1d(N->32, k=3, pad=1) -> ReLU -> partial sum over a 64-l slab.
// grid (8, B): blockIdx.x = slab h, blockIdx.y = b. 256 threads (8 warps).
// Warp w owns output channels o0..o0+3 (o0 = 4w); lane = l within 32-wide tile.
// ============================================================================
__global__ __launch_bounds__(256) void conv_pool_kernel(
    const float* __restrict__ x, const float* __restrict__ conv_w,
    const float* __restrict__ conv_b) {
    // sx: 34 rows x 64 floats, pitch 17 float4 => conflict-free lane-varying LDS.128
    __shared__ float4 sx4[34 * 17];
    __shared__ float4 sw4[32 * 3 * 16];  // [o][k][i] layout, broadcast reads

    const int t = threadIdx.x;
    const int h = blockIdx.x, b = blockIdx.y;

    // Load conv_w (32,64,3) -> sw[o][k][i]
    for (int u = t; u < 32 * 64 * 3; u += 256) {
        int o = u / 192;
        int rem = u % 192;
        int i = rem / 3;
        int k = rem % 3;
        reinterpret_cast<float*>(sw4)[(o * 3 + k) * 64 + i] = conv_w[u];
    }

    const int w = t >> 5, lane = t & 31;
    const int o0 = w * 4;
    const float cb0 = conv_b[o0 + 0], cb1 = conv_b[o0 + 1];
    const float cb2 = conv_b[o0 + 2], cb3 = conv_b[o0 + 3];
    float pool0 = 0.f, pool1 = 0.f, pool2 = 0.f, pool3 = 0.f;
    const float4* x4 = reinterpret_cast<const float4*>(x);

    for (int tile = 0; tile < 2; tile++) {
        const int row0 = h * 64 + tile * 32 - 1;  // first global row of slab
        __syncthreads();  // protects sw (iter 0) and previous tile's sx reads
        for (int u = t; u < 34 * 16; u += 256) {
            int r = u >> 4, i4 = u & 15;
            int gr = row0 + r;
            float4 v = make_float4(0.f, 0.f, 0.f, 0.f);
            if (gr >= 0 && gr < LL) v = x4[(b * LL + gr) * 16 + i4];
            sx4[r * 17 + i4] = v;
        }
        __syncthreads();

        unsigned long long acc0 = 0ull, acc1 = 0ull, acc2 = 0ull, acc3 = 0ull;
#pragma unroll
        for (int k = 0; k < 3; k++) {
#pragma unroll
            for (int i4 = 0; i4 < 16; i4++) {
                float4 xv = sx4[(lane + k) * 17 + i4];
                ulonglong2 xp = as_ull2(xv);
                float4 wv0 = sw4[((o0 + 0) * 3 + k) * 16 + i4];
                float4 wv1 = sw4[((o0 + 1) * 3 + k) * 16 + i4];
                float4 wv2 = sw4[((o0 + 2) * 3 + k) * 16 + i4];
                float4 wv3 = sw4[((o0 + 3) * 3 + k) * 16 + i4];
                ulonglong2 w0 = as_ull2(wv0), w1 = as_ull2(wv1);
                ulonglong2 w2 = as_ull2(wv2), w3 = as_ull2(wv3);
                fma2(acc0, xp.x, w0.x);
                fma2(acc0, xp.y, w0.y);
                fma2(acc1, xp.x, w1.x);
                fma2(acc1, xp.y, w1.y);
                fma2(acc2, xp.x, w2.x);
                fma2(acc2, xp.y, w2.y);
                fma2(acc3, xp.x, w3.x);
                fma2(acc3, xp.y, w3.y);
            }
        }
        {
            float2 a0 = as_f2(acc0), a1 = as_f2(acc1), a2 = as_f2(acc2), a3 = as_f2(acc3);
            pool0 += fmaxf(a0.x + a0.y + cb0, 0.f);
            pool1 += fmaxf(a1.x + a1.y + cb1, 0.f);
            pool2 += fmaxf(a2.x + a2.y + cb2, 0.f);
            pool3 += fmaxf(a3.x + a3.y + cb3, 0.f);
        }
    }

    // warp-reduce over the 32 lanes (sum over this slab's 64 l positions)
#pragma unroll
    for (int off = 16; off > 0; off >>= 1) {
        pool0 += __shfl_xor_sync(0xffffffffu, pool0, off);
        pool1 += __shfl_xor_sync(0xffffffffu, pool1, off);
        pool2 += __shfl_xor_sync(0xffffffffu, pool2, off);
        pool3 += __shfl_xor_sync(0xffffffffu, pool3, off);
    }
    if (lane == 0) {
        float* dst = g_partial + (b * 8 + h) * 32 + o0;
        dst[0] = pool0;
        dst[1] = pool1;
        dst[2] = pool2;
        dst[3] = pool3;
    }
}

// ============================================================================
// Kernel 2 (fused): delta + bilinear gather + patch projection.
// grid (A/2, B, 2): one block per (2 anchors, b, n-half). 256 threads, 8 warps.
// Warps 0/1 each compute delta for one of the 2 anchors; all warps stage
// wp_w -> smem once, then the mainloop runs twice (once per anchor),
// amortizing the 16KB wp_w L2 read over 2x the output.
// Warp w owns 4 n-rows: n = h*32 + w*4 + r. Lane owns d = lane*4 + {0,128}.
// ============================================================================
__global__ __launch_bounds__(256, 3) void patch_kernel(
    const float* __restrict__ x, const float* __restrict__ lin_w,
    const float* __restrict__ lin_b, const float* __restrict__ wp_w,
    const float* __restrict__ wp_b, float* __restrict__ out) {
    __shared__ float s_samp[2][PPP][32];
    __shared__ float s_wp[PPP][DDD];
    __shared__ float s_delta[2];

    const int t = threadIdx.x;
    const int a0 = blockIdx.x * 2, b = blockIdx.y, h = blockIdx.z;
    const int w = t >> 5, lane = t & 31;

    // warps 0,1: delta(b, a0+w) = 4*tanh(mean-pool . lin_w[a] + lin_b[a])
    if (w < 2) {
        const int a = a0 + w;
        float pooled = 0.f;
#pragma unroll
        for (int s = 0; s < 8; s++) pooled += g_partial[(b * 8 + s) * 32 + lane];
        pooled *= (1.0f / 512.0f);
        float term = pooled * lin_w[a * 32 + lane];
#pragma unroll
        for (int off = 16; off > 0; off >>= 1)
            term += __shfl_xor_sync(0xffffffffu, term, off);
        if (lane == 0) s_delta[w] = 4.0f * tanhf(term + lin_b[a]);
    }

    // all warps: stage wp_w (D,P) -> s_wp[p][d]; coalesced global read
    for (int u = t; u < DDD * PPP; u += 256) s_wp[u & 15][u >> 4] = wp_w[u];
    __syncthreads();

    // bilinear sampling: 2a x 16p x 32n values, 4 per thread
    {
        const int nl = t & 31;          // local n
        const int n = h * 32 + nl;      // global n
        const int p0 = t >> 5;          // 0..7
        const float* xb = x + (size_t)b * LL * NNCH;
#pragma unroll
        for (int ai = 0; ai < 2; ai++) {
            const float base = (float)((a0 + ai) * 8) + s_delta[ai] - 7.5f;
#pragma unroll
            for (int j = 0; j < 2; j++) {
                int p = p0 + j * 8;
                float xs = base + (float)p;
                xs = fminf(fmaxf(xs, 0.f), 511.f);
                float fl = floorf(xs);
                int i0 = (int)fl;
                float f = xs - fl;
                int i1 = min(i0 + 1, LL - 1);
                s_samp[ai][p][nl] =
                    xb[i0 * NNCH + n] * (1.0f - f) + xb[i1 * NNCH + n] * f;
            }
        }
    }
    __syncthreads();

    const float4* wb4 = reinterpret_cast<const float4*>(wp_b);
    float4 bias0 = wb4[lane];       // d = lane*4 .. +3
    float4 bias1 = wb4[lane + 32];  // d = 128 + lane*4 .. +3
    const ulonglong2 bb0 = as_ull2(bias0), bb1 = as_ull2(bias1);

#pragma unroll
    for (int ai = 0; ai < 2; ai++) {
        unsigned long long acc[4][4];
#pragma unroll
        for (int r = 0; r < 4; r++) {
            acc[r][0] = bb0.x;
            acc[r][1] = bb0.y;
            acc[r][2] = bb1.x;
            acc[r][3] = bb1.y;
        }

#pragma unroll
        for (int p = 0; p < PPP; p++) {
            float4 w0 = *reinterpret_cast<const float4*>(&s_wp[p][lane * 4]);
            float4 w1 = *reinterpret_cast<const float4*>(&s_wp[p][128 + lane * 4]);
            ulonglong2 wA = as_ull2(w0), wB = as_ull2(w1);
            // ONE broadcast LDS.128 brings the 4 samp rows this warp owns
            float4 s4 = *reinterpret_cast<const float4*>(&s_samp[ai][p][w * 4]);
            unsigned long long s0 = dup2(s4.x), s1 = dup2(s4.y);
            unsigned long long s2 = dup2(s4.z), s3 = dup2(s4.w);
            fma2(acc[0][0], s0, wA.x);
            fma2(acc[0][1], s0, wA.y);
            fma2(acc[0][2], s0, wB.x);
            fma2(acc[0][3], s0, wB.y);
            fma2(acc[1][0], s1, wA.x);
            fma2(acc[1][1], s1, wA.y);
            fma2(acc[1][2], s1, wB.x);
            fma2(acc[1][3], s1, wB.y);
            fma2(acc[2][0], s2, wA.x);
            fma2(acc[2][1], s2, wA.y);
            fma2(acc[2][2], s2, wB.x);
            fma2(acc[2][3], s2, wB.y);
            fma2(acc[3][0], s3, wA.x);
            fma2(acc[3][1], s3, wA.y);
            fma2(acc[3][2], s3, wB.x);
            fma2(acc[3][3], s3, wB.y);
        }

#pragma unroll
        for (int r = 0; r < 4; r++) {
            const int n = h * 32 + w * 4 + r;
            float* op = out + (((size_t)(b * 64 + n) * 64 + (a0 + ai)) * 256);
            float2 l0 = as_f2(acc[r][0]), l1 = as_f2(acc[r][1]);
            float2 h0 = as_f2(acc[r][2]), h1 = as_f2(acc[r][3]);
            float4 v0 = make_float4(l0.x, l0.y, l1.x, l1.y);
            float4 v1 = make_float4(h0.x, h0.y, h1.x, h1.y);
            __stcs(reinterpret_cast<float4*>(op + lane * 4), v0);
            __stcs(reinterpret_cast<float4*>(op + 128 + lane * 4), v1);
        }
    }
}

// ============================================================================
extern "C" void kernel_launch(void* const* d_in, const int* in_sizes, int n_in,
                              void* d_out, int out_size) {
    const float* x = (const float*)d_in[0];
    const float* conv_w = (const float*)d_in[1];
    const float* conv_b = (const float*)d_in[2];
    const float* lin_w = (const float*)d_in[3];
    const float* lin_b = (const float*)d_in[4];
    const float* wp_w = (const float*)d_in[5];
    const float* wp_b = (const float*)d_in[6];

    conv_pool_kernel<<<dim3(8, BB), 256>>>(x, conv_w, conv_b);
    patch_kernel<<<dim3(AAA / 2, BB, 2), 256>>>(x, lin_w, lin_b, wp_w, wp_b,
                                                (float*)d_out);
}

// round 6
// speedup vs baseline: 1.7499x; 1.7499x over previous
#include <cuda_runtime.h>
#include <math.h>

// Problem constants (fixed by setup_inputs)
#define BB 64
#define LL 512
#define NNCH 64
#define AAA 64
#define DDD 256
#define PPP 16

// Scratch (no cudaMalloc allowed). conv partials: [b][slab(8)][o(32)]
__device__ float g_partial[BB * 8 * 32];

// -------- packed fp32x2 FMA (Blackwell FFMA2) --------
__device__ __forceinline__ void fma2(unsigned long long& c, unsigned long long a,
                                     unsigned long long b) {
    asm("fma.rn.f32x2 %0, %1, %2, %0;" : "+l"(c) : "l"(a), "l"(b));
}
__device__ __forceinline__ ulonglong2 as_ull2(float4 v) {
    return *reinterpret_cast<ulonglong2*>(&v);
}
__device__ __forceinline__ float2 as_f2(unsigned long long v) {
    return *reinterpret_cast<float2*>(&v);
}
__device__ __forceinline__ unsigned long long dup2(float s) {
    float2 t = make_float2(s, s);
    return *reinterpret_cast<unsigned long long*>(&t);
}

// ============================================================================
// Kernel 1: Conv1d(N->32, k=3, pad=1) -> ReLU -> partial sum over a 64-l slab.
// grid (8, B): blockIdx.x = slab h, blockIdx.y = b. 256 threads (8 warps).
// Warp w owns output channels o0..o0+3 (o0 = 4w); lane = l within 32-wide tile.
// ============================================================================
__global__ __launch_bounds__(256) void conv_pool_kernel(
    const float* __restrict__ x, const float* __restrict__ conv_w,
    const float* __restrict__ conv_b) {
    // sx: 34 rows x 64 floats, pitch 17 float4 => conflict-free lane-varying LDS.128
    __shared__ float4 sx4[34 * 17];
    __shared__ float4 sw4[32 * 3 * 16];  // [o][k][i] layout, broadcast reads

    const int t = threadIdx.x;
    const int h = blockIdx.x, b = blockIdx.y;

    // Load conv_w (32,64,3) -> sw[o][k][i]
    for (int u = t; u < 32 * 64 * 3; u += 256) {
        int o = u / 192;
        int rem = u % 192;
        int i = rem / 3;
        int k = rem % 3;
        reinterpret_cast<float*>(sw4)[(o * 3 + k) * 64 + i] = conv_w[u];
    }

    const int w = t >> 5, lane = t & 31;
    const int o0 = w * 4;
    const float cb0 = conv_b[o0 + 0], cb1 = conv_b[o0 + 1];
    const float cb2 = conv_b[o0 + 2], cb3 = conv_b[o0 + 3];
    float pool0 = 0.f, pool1 = 0.f, pool2 = 0.f, pool3 = 0.f;
    const float4* x4 = reinterpret_cast<const float4*>(x);

    for (int tile = 0; tile < 2; tile++) {
        const int row0 = h * 64 + tile * 32 - 1;  // first global row of slab
        __syncthreads();  // protects sw (iter 0) and previous tile's sx reads
        for (int u = t; u < 34 * 16; u += 256) {
            int r = u >> 4, i4 = u & 15;
            int gr = row0 + r;
            float4 v = make_float4(0.f, 0.f, 0.f, 0.f);
            if (gr >= 0 && gr < LL) v = x4[(b * LL + gr) * 16 + i4];
            sx4[r * 17 + i4] = v;
        }
        __syncthreads();

        unsigned long long acc0 = 0ull, acc1 = 0ull, acc2 = 0ull, acc3 = 0ull;
#pragma unroll
        for (int k = 0; k < 3; k++) {
#pragma unroll
            for (int i4 = 0; i4 < 16; i4++) {
                float4 xv = sx4[(lane + k) * 17 + i4];
                ulonglong2 xp = as_ull2(xv);
                float4 wv0 = sw4[((o0 + 0) * 3 + k) * 16 + i4];
                float4 wv1 = sw4[((o0 + 1) * 3 + k) * 16 + i4];
                float4 wv2 = sw4[((o0 + 2) * 3 + k) * 16 + i4];
                float4 wv3 = sw4[((o0 + 3) * 3 + k) * 16 + i4];
                ulonglong2 w0 = as_ull2(wv0), w1 = as_ull2(wv1);
                ulonglong2 w2 = as_ull2(wv2), w3 = as_ull2(wv3);
                fma2(acc0, xp.x, w0.x);
                fma2(acc0, xp.y, w0.y);
                fma2(acc1, xp.x, w1.x);
                fma2(acc1, xp.y, w1.y);
                fma2(acc2, xp.x, w2.x);
                fma2(acc2, xp.y, w2.y);
                fma2(acc3, xp.x, w3.x);
                fma2(acc3, xp.y, w3.y);
            }
        }
        {
            float2 a0 = as_f2(acc0), a1 = as_f2(acc1), a2 = as_f2(acc2), a3 = as_f2(acc3);
            pool0 += fmaxf(a0.x + a0.y + cb0, 0.f);
            pool1 += fmaxf(a1.x + a1.y + cb1, 0.f);
            pool2 += fmaxf(a2.x + a2.y + cb2, 0.f);
            pool3 += fmaxf(a3.x + a3.y + cb3, 0.f);
        }
    }

    // warp-reduce over the 32 lanes (sum over this slab's 64 l positions)
#pragma unroll
    for (int off = 16; off > 0; off >>= 1) {
        pool0 += __shfl_xor_sync(0xffffffffu, pool0, off);
        pool1 += __shfl_xor_sync(0xffffffffu, pool1, off);
        pool2 += __shfl_xor_sync(0xffffffffu, pool2, off);
        pool3 += __shfl_xor_sync(0xffffffffu, pool3, off);
    }
    if (lane == 0) {
        float* dst = g_partial + (b * 8 + h) * 32 + o0;
        dst[0] = pool0;
        dst[1] = pool1;
        dst[2] = pool2;
        dst[3] = pool3;
    }
}

// ============================================================================
// Kernel 2 (fused): delta + bilinear gather + patch projection.
// grid (A/2, B, 2): one block per (2 anchors, b, n-half). 256 threads, 8 warps.
// NO min-blocks clamp (R5's __launch_bounds__(256,3) caused register spills ->
// ~800MB of local-memory DRAM traffic). Bias is staged in smem, not held in
// registers across the mainloop, to keep live state ~72-78 regs.
// Warp w owns 4 n-rows: n = h*32 + w*4 + r. Lane owns d = lane*4 + {0,128}.
// ============================================================================
__global__ __launch_bounds__(256) void patch_kernel(
    const float* __restrict__ x, const float* __restrict__ lin_w,
    const float* __restrict__ lin_b, const float* __restrict__ wp_w,
    const float* __restrict__ wp_b, float* __restrict__ out) {
    __shared__ float s_samp[2][PPP][32];
    __shared__ float s_wp[PPP][DDD];
    __shared__ float s_wb[DDD];
    __shared__ float s_delta[2];

    const int t = threadIdx.x;
    const int a0 = blockIdx.x * 2, b = blockIdx.y, h = blockIdx.z;
    const int w = t >> 5, lane = t & 31;

    // warps 0,1: delta(b, a0+w) = 4*tanh(mean-pool . lin_w[a] + lin_b[a])
    if (w < 2) {
        const int a = a0 + w;
        float pooled = 0.f;
#pragma unroll
        for (int s = 0; s < 8; s++) pooled += g_partial[(b * 8 + s) * 32 + lane];
        pooled *= (1.0f / 512.0f);
        float term = pooled * lin_w[a * 32 + lane];
#pragma unroll
        for (int off = 16; off > 0; off >>= 1)
            term += __shfl_xor_sync(0xffffffffu, term, off);
        if (lane == 0) s_delta[w] = 4.0f * tanhf(term + lin_b[a]);
    }

    // all warps: stage wp_w (D,P) -> s_wp[p][d], and wp_b -> s_wb
    for (int u = t; u < DDD * PPP; u += 256) s_wp[u & 15][u >> 4] = wp_w[u];
    if (t < DDD / 4)
        reinterpret_cast<float4*>(s_wb)[t] =
            reinterpret_cast<const float4*>(wp_b)[t];
    __syncthreads();

    // bilinear sampling: 2a x 16p x 32n values, 4 per thread
    {
        const int nl = t & 31;          // local n
        const int n = h * 32 + nl;      // global n
        const int p0 = t >> 5;          // 0..7
        const float* xb = x + (size_t)b * LL * NNCH;
#pragma unroll
        for (int ai = 0; ai < 2; ai++) {
            const float base = (float)((a0 + ai) * 8) + s_delta[ai] - 7.5f;
#pragma unroll
            for (int j = 0; j < 2; j++) {
                int p = p0 + j * 8;
                float xs = base + (float)p;
                xs = fminf(fmaxf(xs, 0.f), 511.f);
                float fl = floorf(xs);
                int i0 = (int)fl;
                float f = xs - fl;
                int i1 = min(i0 + 1, LL - 1);
                s_samp[ai][p][nl] =
                    xb[i0 * NNCH + n] * (1.0f - f) + xb[i1 * NNCH + n] * f;
            }
        }
    }
    __syncthreads();

#pragma unroll
    for (int ai = 0; ai < 2; ai++) {
        // acc init = bias, re-read from smem each anchor (keeps regs low)
        float4 bias0 = *reinterpret_cast<const float4*>(&s_wb[lane * 4]);
        float4 bias1 = *reinterpret_cast<const float4*>(&s_wb[128 + lane * 4]);
        ulonglong2 bb0 = as_ull2(bias0), bb1 = as_ull2(bias1);
        unsigned long long acc[4][4];
#pragma unroll
        for (int r = 0; r < 4; r++) {
            acc[r][0] = bb0.x;
            acc[r][1] = bb0.y;
            acc[r][2] = bb1.x;
            acc[r][3] = bb1.y;
        }

#pragma unroll
        for (int p = 0; p < PPP; p++) {
            float4 w0 = *reinterpret_cast<const float4*>(&s_wp[p][lane * 4]);
            float4 w1 = *reinterpret_cast<const float4*>(&s_wp[p][128 + lane * 4]);
            ulonglong2 wA = as_ull2(w0), wB = as_ull2(w1);
            // ONE broadcast LDS.128 brings the 4 samp rows this warp owns
            float4 s4 = *reinterpret_cast<const float4*>(&s_samp[ai][p][w * 4]);
            unsigned long long s0 = dup2(s4.x), s1 = dup2(s4.y);
            unsigned long long s2 = dup2(s4.z), s3 = dup2(s4.w);
            fma2(acc[0][0], s0, wA.x);
            fma2(acc[0][1], s0, wA.y);
            fma2(acc[0][2], s0, wB.x);
            fma2(acc[0][3], s0, wB.y);
            fma2(acc[1][0], s1, wA.x);
            fma2(acc[1][1], s1, wA.y);
            fma2(acc[1][2], s1, wB.x);
            fma2(acc[1][3], s1, wB.y);
            fma2(acc[2][0], s2, wA.x);
            fma2(acc[2][1], s2, wA.y);
            fma2(acc[2][2], s2, wB.x);
            fma2(acc[2][3], s2, wB.y);
            fma2(acc[3][0], s3, wA.x);
            fma2(acc[3][1], s3, wA.y);
            fma2(acc[3][2], s3, wB.x);
            fma2(acc[3][3], s3, wB.y);
        }

#pragma unroll
        for (int r = 0; r < 4; r++) {
            const int n = h * 32 + w * 4 + r;
            float* op = out + (((size_t)(b * 64 + n) * 64 + (a0 + ai)) * 256);
            float2 l0 = as_f2(acc[r][0]), l1 = as_f2(acc[r][1]);
            float2 h0 = as_f2(acc[r][2]), h1 = as_f2(acc[r][3]);
            float4 v0 = make_float4(l0.x, l0.y, l1.x, l1.y);
            float4 v1 = make_float4(h0.x, h0.y, h1.x, h1.y);
            __stcs(reinterpret_cast<float4*>(op + lane * 4), v0);
            __stcs(reinterpret_cast<float4*>(op + 128 + lane * 4), v1);
        }
    }
}

// ============================================================================
extern "C" void kernel_launch(void* const* d_in, const int* in_sizes, int n_in,
                              void* d_out, int out_size) {
    const float* x = (const float*)d_in[0];
    const float* conv_w = (const float*)d_in[1];
    const float* conv_b = (const float*)d_in[2];
    const float* lin_w = (const float*)d_in[3];
    const float* lin_b = (const float*)d_in[4];
    const float* wp_w = (const float*)d_in[5];
    const float* wp_b = (const float*)d_in[6];

    conv_pool_kernel<<<dim3(8, BB), 256>>>(x, conv_w, conv_b);
    patch_kernel<<<dim3(AAA / 2, BB, 2), 256>>>(x, lin_w, lin_b, wp_w, wp_b,
                                                (float*)d_out);
}

// round 7
// speedup vs baseline: 1.8249x; 1.0428x over previous
#include <cuda_runtime.h>
#include <math.h>

// Problem constants (fixed by setup_inputs)
#define BB 64
#define LL 512
#define NNCH 64
#define AAA 64
#define DDD 256
#define PPP 16

// Scratch (no cudaMalloc allowed). conv partials: [b][slab(8)][o(32)]
__device__ float g_partial[BB * 8 * 32];

// -------- packed fp32x2 FMA (Blackwell FFMA2) --------
__device__ __forceinline__ void fma2(unsigned long long& c, unsigned long long a,
                                     unsigned long long b) {
    asm("fma.rn.f32x2 %0, %1, %2, %0;" : "+l"(c) : "l"(a), "l"(b));
}
__device__ __forceinline__ ulonglong2 as_ull2(float4 v) {
    return *reinterpret_cast<ulonglong2*>(&v);
}
__device__ __forceinline__ float2 as_f2(unsigned long long v) {
    return *reinterpret_cast<float2*>(&v);
}
__device__ __forceinline__ unsigned long long dup2(float s) {
    unsigned long long r;
    asm("mov.b64 %0, {%1, %1};" : "=l"(r) : "f"(s));
    return r;
}
__device__ __forceinline__ unsigned long long pack2(float lo, float hi) {
    unsigned long long r;
    asm("mov.b64 %0, {%1, %2};" : "=l"(r) : "f"(lo), "f"(hi));
    return r;
}

// ============================================================================
// Kernel 1: Conv1d(N->32, k=3, pad=1) -> ReLU -> partial sum over a 64-l slab.
// grid (8, B). 256 threads (8 warps). Warp w owns channels 4w..4w+3.
// ============================================================================
__global__ __launch_bounds__(256) void conv_pool_kernel(
    const float* __restrict__ x, const float* __restrict__ conv_w,
    const float* __restrict__ conv_b) {
    __shared__ float4 sx4[34 * 17];      // pitch 17 float4 -> conflict-free
    __shared__ float4 sw4[32 * 3 * 16];  // [o][k][i] layout, broadcast reads

    const int t = threadIdx.x;
    const int h = blockIdx.x, b = blockIdx.y;

    for (int u = t; u < 32 * 64 * 3; u += 256) {
        int o = u / 192;
        int rem = u % 192;
        int i = rem / 3;
        int k = rem % 3;
        reinterpret_cast<float*>(sw4)[(o * 3 + k) * 64 + i] = conv_w[u];
    }

    const int w = t >> 5, lane = t & 31;
    const int o0 = w * 4;
    const float cb0 = conv_b[o0 + 0], cb1 = conv_b[o0 + 1];
    const float cb2 = conv_b[o0 + 2], cb3 = conv_b[o0 + 3];
    float pool0 = 0.f, pool1 = 0.f, pool2 = 0.f, pool3 = 0.f;
    const float4* x4 = reinterpret_cast<const float4*>(x);

    for (int tile = 0; tile < 2; tile++) {
        const int row0 = h * 64 + tile * 32 - 1;
        __syncthreads();
        for (int u = t; u < 34 * 16; u += 256) {
            int r = u >> 4, i4 = u & 15;
            int gr = row0 + r;
            float4 v = make_float4(0.f, 0.f, 0.f, 0.f);
            if (gr >= 0 && gr < LL) v = x4[(b * LL + gr) * 16 + i4];
            sx4[r * 17 + i4] = v;
        }
        __syncthreads();

        unsigned long long acc0 = 0ull, acc1 = 0ull, acc2 = 0ull, acc3 = 0ull;
#pragma unroll
        for (int k = 0; k < 3; k++) {
#pragma unroll
            for (int i4 = 0; i4 < 16; i4++) {
                float4 xv = sx4[(lane + k) * 17 + i4];
                ulonglong2 xp = as_ull2(xv);
                float4 wv0 = sw4[((o0 + 0) * 3 + k) * 16 + i4];
                float4 wv1 = sw4[((o0 + 1) * 3 + k) * 16 + i4];
                float4 wv2 = sw4[((o0 + 2) * 3 + k) * 16 + i4];
                float4 wv3 = sw4[((o0 + 3) * 3 + k) * 16 + i4];
                ulonglong2 w0 = as_ull2(wv0), w1 = as_ull2(wv1);
                ulonglong2 w2 = as_ull2(wv2), w3 = as_ull2(wv3);
                fma2(acc0, xp.x, w0.x);
                fma2(acc0, xp.y, w0.y);
                fma2(acc1, xp.x, w1.x);
                fma2(acc1, xp.y, w1.y);
                fma2(acc2, xp.x, w2.x);
                fma2(acc2, xp.y, w2.y);
                fma2(acc3, xp.x, w3.x);
                fma2(acc3, xp.y, w3.y);
            }
        }
        {
            float2 a0 = as_f2(acc0), a1 = as_f2(acc1), a2 = as_f2(acc2), a3 = as_f2(acc3);
            pool0 += fmaxf(a0.x + a0.y + cb0, 0.f);
            pool1 += fmaxf(a1.x + a1.y + cb1, 0.f);
            pool2 += fmaxf(a2.x + a2.y + cb2, 0.f);
            pool3 += fmaxf(a3.x + a3.y + cb3, 0.f);
        }
    }

#pragma unroll
    for (int off = 16; off > 0; off >>= 1) {
        pool0 += __shfl_xor_sync(0xffffffffu, pool0, off);
        pool1 += __shfl_xor_sync(0xffffffffu, pool1, off);
        pool2 += __shfl_xor_sync(0xffffffffu, pool2, off);
        pool3 += __shfl_xor_sync(0xffffffffu, pool3, off);
    }
    if (lane == 0) {
        float* dst = g_partial + (b * 8 + h) * 32 + o0;
        dst[0] = pool0;
        dst[1] = pool1;
        dst[2] = pool2;
        dst[3] = pool3;
    }
}

// ============================================================================
// Kernel 2: delta + bilinear gather + patch projection, weights IN REGISTERS.
// grid (A/2, B, 2): block = (2 anchors, b, 32-row n-half). 256 threads, 8 warps.
// Each thread owns 4 d-columns (d0 = (w&1)*128 + lane*4) and holds all 16
// patch-weights for them in 64 registers (loaded once from L2-hot wp_w).
// Warp pair q = w>>1 processes rows q*8..q*8+7 for both anchors; per
// (row,anchor): 4 broadcast LDS.128 of samp + 32 FFMA2 (two interleaved
// dependency chains -> saturates FMA pipe) + 1 STG.128.
// launch_bounds(256,2): cap 128 regs >= ~108 natural demand -> no spills,
// 2 blocks/SM.
// ============================================================================
__global__ __launch_bounds__(256, 2) void patch_kernel(
    const float* __restrict__ x, const float* __restrict__ lin_w,
    const float* __restrict__ lin_b, const float* __restrict__ wp_w,
    const float* __restrict__ wp_b, float* __restrict__ out) {
    // samp transposed: [ai][n][p], padded to 20 (16B-aligned rows, low conflicts)
    __shared__ float s_samp[2][32][20];
    __shared__ float s_delta[2];

    const int t = threadIdx.x;
    const int a0 = blockIdx.x * 2, b = blockIdx.y, h = blockIdx.z;
    const int w = t >> 5, lane = t & 31;
    const int dh = w & 1;   // d half: 0 -> d 0..127, 1 -> d 128..255
    const int q = w >> 1;   // row group: rows q*8 .. q*8+7
    const int d0 = dh * 128 + lane * 4;

    // ---- weight preload: 16 LDG.128 -> 64 regs, then pack into f32x2 pairs --
    float4 wv0[4], wv1[4], wv2[4], wv3[4];  // [j][p4] : row d0+j, p4*4..p4*4+3
    const float4* wpw4 = reinterpret_cast<const float4*>(wp_w);
#pragma unroll
    for (int p4 = 0; p4 < 4; p4++) {
        wv0[p4] = wpw4[(d0 + 0) * 4 + p4];
        wv1[p4] = wpw4[(d0 + 1) * 4 + p4];
        wv2[p4] = wpw4[(d0 + 2) * 4 + p4];
        wv3[p4] = wpw4[(d0 + 3) * 4 + p4];
    }
    float4 bias = reinterpret_cast<const float4*>(wp_b)[d0 >> 2];

    // ---- warps 0,1: delta(b, a0+w) ----
    if (w < 2) {
        const int a = a0 + w;
        float pooled = 0.f;
#pragma unroll
        for (int s = 0; s < 8; s++) pooled += g_partial[(b * 8 + s) * 32 + lane];
        pooled *= (1.0f / 512.0f);
        float term = pooled * lin_w[a * 32 + lane];
#pragma unroll
        for (int off = 16; off > 0; off >>= 1)
            term += __shfl_xor_sync(0xffffffffu, term, off);
        if (lane == 0) s_delta[w] = 4.0f * tanhf(term + lin_b[a]);
    }

    // pack weights: wpair01[p] = (w[d0][p], w[d0+1][p]); wpair23 likewise
    unsigned long long wp01[PPP], wp23[PPP];
#pragma unroll
    for (int p = 0; p < PPP; p++) {
        const int p4 = p >> 2, pc = p & 3;
        float a01lo = reinterpret_cast<const float*>(&wv0[p4])[pc];
        float a01hi = reinterpret_cast<const float*>(&wv1[p4])[pc];
        float a23lo = reinterpret_cast<const float*>(&wv2[p4])[pc];
        float a23hi = reinterpret_cast<const float*>(&wv3[p4])[pc];
        wp01[p] = pack2(a01lo, a01hi);
        wp23[p] = pack2(a23lo, a23hi);
    }
    const unsigned long long bb01 = pack2(bias.x, bias.y);
    const unsigned long long bb23 = pack2(bias.z, bias.w);
    __syncthreads();  // s_delta visible

    // ---- bilinear sampling: 2a x 32n x 16p, 4 values per thread ----
    {
        const int nl = t & 31;
        const int n = h * 32 + nl;
        const int p0 = t >> 5;  // 0..7
        const float* xb = x + (size_t)b * LL * NNCH;
#pragma unroll
        for (int ai = 0; ai < 2; ai++) {
            const float base = (float)((a0 + ai) * 8) + s_delta[ai] - 7.5f;
#pragma unroll
            for (int j = 0; j < 2; j++) {
                int p = p0 + j * 8;
                float xs = base + (float)p;
                xs = fminf(fmaxf(xs, 0.f), 511.f);
                float fl = floorf(xs);
                int i0 = (int)fl;
                float f = xs - fl;
                int i1 = min(i0 + 1, LL - 1);
                s_samp[ai][nl][p] =
                    xb[i0 * NNCH + n] * (1.0f - f) + xb[i1 * NNCH + n] * f;
            }
        }
    }
    __syncthreads();

    // ---- mainloop: 16 (row, anchor) combos per warp ----
#pragma unroll 1
    for (int c = 0; c < 16; c++) {
        const int ai = c >> 3;
        const int r = c & 7;
        const int row = q * 8 + r;
        const float* sp = &s_samp[ai][row][0];
        float4 sa = *reinterpret_cast<const float4*>(sp + 0);
        float4 sb = *reinterpret_cast<const float4*>(sp + 4);
        float4 sc = *reinterpret_cast<const float4*>(sp + 8);
        float4 sd = *reinterpret_cast<const float4*>(sp + 12);

        unsigned long long acc01 = bb01, acc23 = bb23;
#define PSTEP(sv, p)                      \
    {                                     \
        unsigned long long s2 = dup2(sv); \
        fma2(acc01, s2, wp01[p]);         \
        fma2(acc23, s2, wp23[p]);         \
    }
        PSTEP(sa.x, 0)
        PSTEP(sa.y, 1)
        PSTEP(sa.z, 2)
        PSTEP(sa.w, 3)
        PSTEP(sb.x, 4)
        PSTEP(sb.y, 5)
        PSTEP(sb.z, 6)
        PSTEP(sb.w, 7)
        PSTEP(sc.x, 8)
        PSTEP(sc.y, 9)
        PSTEP(sc.z, 10)
        PSTEP(sc.w, 11)
        PSTEP(sd.x, 12)
        PSTEP(sd.y, 13)
        PSTEP(sd.z, 14)
        PSTEP(sd.w, 15)
#undef PSTEP

        const int n = h * 32 + row;
        float* op =
            out + (((size_t)(b * 64 + n) * 64 + (a0 + ai)) * 256) + d0;
        float2 l0 = as_f2(acc01), l1 = as_f2(acc23);
        __stcs(reinterpret_cast<float4*>(op),
               make_float4(l0.x, l0.y, l1.x, l1.y));
    }
}

// ============================================================================
extern "C" void kernel_launch(void* const* d_in, const int* in_sizes, int n_in,
                              void* d_out, int out_size) {
    const float* x = (const float*)d_in[0];
    const float* conv_w = (const float*)d_in[1];
    const float* conv_b = (const float*)d_in[2];
    const float* lin_w = (const float*)d_in[3];
    const float* lin_b = (const float*)d_in[4];
    const float* wp_w = (const float*)d_in[5];
    const float* wp_b = (const float*)d_in[6];

    conv_pool_kernel<<<dim3(8, BB), 256>>>(x, conv_w, conv_b);
    patch_kernel<<<dim3(AAA / 2, BB, 2), 256>>>(x, lin_w, lin_b, wp_w, wp_b,
                                                (float*)d_out);
}

// round 10
// speedup vs baseline: 2.7801x; 1.5234x over previous
#include <cuda_runtime.h>
#include <math.h>

// Problem constants (fixed by setup_inputs)
#define BB 64
#define LL 512
#define NNCH 64
#define AAA 64
#define DDD 256
#define PPP 16

// Scratch (no cudaMalloc allowed). conv partials: [b][slab(8)][o(32)]
__device__ float g_partial[BB * 8 * 32];

// -------- packed fp32x2 FMA (Blackwell FFMA2) --------
__device__ __forceinline__ void fma2(unsigned long long& c, unsigned long long a,
                                     unsigned long long b) {
    asm("fma.rn.f32x2 %0, %1, %2, %0;" : "+l"(c) : "l"(a), "l"(b));
}
__device__ __forceinline__ ulonglong2 as_ull2(float4 v) {
    return *reinterpret_cast<ulonglong2*>(&v);
}
__device__ __forceinline__ float2 as_f2(unsigned long long v) {
    return *reinterpret_cast<float2*>(&v);
}
__device__ __forceinline__ unsigned long long dup2(float s) {
    unsigned long long r;
    asm("mov.b64 %0, {%1, %1};" : "=l"(r) : "f"(s));
    return r;
}
__device__ __forceinline__ unsigned long long pack2(float lo, float hi) {
    unsigned long long r;
    asm("mov.b64 %0, {%1, %2};" : "=l"(r) : "f"(lo), "f"(hi));
    return r;
}

// ============================================================================
// Kernel 1: Conv1d(N->32, k=3, pad=1) -> ReLU -> partial sum over a 64-l slab.
// grid (8, B). 256 threads (8 warps). Warp w owns channels 4w..4w+3.
// ============================================================================
__global__ __launch_bounds__(256) void conv_pool_kernel(
    const float* __restrict__ x, const float* __restrict__ conv_w,
    const float* __restrict__ conv_b) {
    __shared__ float4 sx4[34 * 17];      // pitch 17 float4 -> conflict-free
    __shared__ float4 sw4[32 * 3 * 16];  // [o][k][i] layout, broadcast reads

    const int t = threadIdx.x;
    const int h = blockIdx.x, b = blockIdx.y;

    for (int u = t; u < 32 * 64 * 3; u += 256) {
        int o = u / 192;
        int rem = u % 192;
        int i = rem / 3;
        int k = rem % 3;
        reinterpret_cast<float*>(sw4)[(o * 3 + k) * 64 + i] = conv_w[u];
    }

    const int w = t >> 5, lane = t & 31;
    const int o0 = w * 4;
    const float cb0 = conv_b[o0 + 0], cb1 = conv_b[o0 + 1];
    const float cb2 = conv_b[o0 + 2], cb3 = conv_b[o0 + 3];
    float pool0 = 0.f, pool1 = 0.f, pool2 = 0.f, pool3 = 0.f;
    const float4* x4 = reinterpret_cast<const float4*>(x);

    for (int tile = 0; tile < 2; tile++) {
        const int row0 = h * 64 + tile * 32 - 1;
        __syncthreads();
        for (int u = t; u < 34 * 16; u += 256) {
            int r = u >> 4, i4 = u & 15;
            int gr = row0 + r;
            float4 v = make_float4(0.f, 0.f, 0.f, 0.f);
            if (gr >= 0 && gr < LL) v = x4[(b * LL + gr) * 16 + i4];
            sx4[r * 17 + i4] = v;
        }
        __syncthreads();

        unsigned long long acc0 = 0ull, acc1 = 0ull, acc2 = 0ull, acc3 = 0ull;
#pragma unroll
        for (int k = 0; k < 3; k++) {
#pragma unroll
            for (int i4 = 0; i4 < 16; i4++) {
                float4 xv = sx4[(lane + k) * 17 + i4];
                ulonglong2 xp = as_ull2(xv);
                float4 wv0 = sw4[((o0 + 0) * 3 + k) * 16 + i4];
                float4 wv1 = sw4[((o0 + 1) * 3 + k) * 16 + i4];
                float4 wv2 = sw4[((o0 + 2) * 3 + k) * 16 + i4];
                float4 wv3 = sw4[((o0 + 3) * 3 + k) * 16 + i4];
                ulonglong2 w0 = as_ull2(wv0), w1 = as_ull2(wv1);
                ulonglong2 w2 = as_ull2(wv2), w3 = as_ull2(wv3);
                fma2(acc0, xp.x, w0.x);
                fma2(acc0, xp.y, w0.y);
                fma2(acc1, xp.x, w1.x);
                fma2(acc1, xp.y, w1.y);
                fma2(acc2, xp.x, w2.x);
                fma2(acc2, xp.y, w2.y);
                fma2(acc3, xp.x, w3.x);
                fma2(acc3, xp.y, w3.y);
            }
        }
        {
            float2 a0 = as_f2(acc0), a1 = as_f2(acc1), a2 = as_f2(acc2), a3 = as_f2(acc3);
            pool0 += fmaxf(a0.x + a0.y + cb0, 0.f);
            pool1 += fmaxf(a1.x + a1.y + cb1, 0.f);
            pool2 += fmaxf(a2.x + a2.y + cb2, 0.f);
            pool3 += fmaxf(a3.x + a3.y + cb3, 0.f);
        }
    }

#pragma unroll
    for (int off = 16; off > 0; off >>= 1) {
        pool0 += __shfl_xor_sync(0xffffffffu, pool0, off);
        pool1 += __shfl_xor_sync(0xffffffffu, pool1, off);
        pool2 += __shfl_xor_sync(0xffffffffu, pool2, off);
        pool3 += __shfl_xor_sync(0xffffffffu, pool3, off);
    }
    if (lane == 0) {
        float* dst = g_partial + (b * 8 + h) * 32 + o0;
        dst[0] = pool0;
        dst[1] = pool1;
        dst[2] = pool2;
        dst[3] = pool3;
    }
}

// ============================================================================
// Kernel 2: delta + bilinear gather + patch projection, weights in registers,
// loaded via COALESCED LDG -> transposed smem -> conflict-free LDS.128.
// (R7's direct per-thread LDG preload was 256B-lane-strided: 32 lines per
// LDG.128 = ~4096 L1 wavefronts/block -> L1 pipe 68% busy. This path is ~6x
// cheaper.)
// grid (A/2, B, 2). 256 threads, 8 warps. Thread owns 4 d-cols
// (d0 = (w&1)*128 + lane*4); warp pair q=w>>1 does rows q*8..q*8+7, both
// anchors. Per combo: 4 broadcast LDS.128 + 32 FFMA2 + 1 STG.128.
// ============================================================================
__global__ __launch_bounds__(256, 2) void patch_kernel(
    const float* __restrict__ x, const float* __restrict__ lin_w,
    const float* __restrict__ lin_b, const float* __restrict__ wp_w,
    const float* __restrict__ wp_b, float* __restrict__ out) {
    __shared__ float s_wpT[PPP][DDD + 4];  // transposed [p][d], pitch 260
    __shared__ float s_samp[2][32][20];    // [ai][n][p], pitch 20 (16B-aligned)
    __shared__ float s_delta[2];

    const int t = threadIdx.x;
    const int a0 = blockIdx.x * 2, b = blockIdx.y, h = blockIdx.z;
    const int w = t >> 5, lane = t & 31;
    const int dh = w & 1;
    const int q = w >> 1;
    const int d0 = dh * 128 + lane * 4;

    // ---- stage wp_w (D,P) -> s_wpT[p][d], coalesced LDG.128 ----
    {
        const float4* wpw4 = reinterpret_cast<const float4*>(wp_w);
#pragma unroll
        for (int c = 0; c < 4; c++) {
            int u4 = t + 256 * c;  // 0..1023
            float4 v = wpw4[u4];   // = wp_w[d][p0..p0+3], d=u4>>2, p0=(u4&3)*4
            int d = u4 >> 2, p0 = (u4 & 3) * 4;
            s_wpT[p0 + 0][d] = v.x;
            s_wpT[p0 + 1][d] = v.y;
            s_wpT[p0 + 2][d] = v.z;
            s_wpT[p0 + 3][d] = v.w;
        }
    }

    // ---- warps 0,1: delta(b, a0+w) ----
    if (w < 2) {
        const int a = a0 + w;
        float pooled = 0.f;
#pragma unroll
        for (int s = 0; s < 8; s++) pooled += g_partial[(b * 8 + s) * 32 + lane];
        pooled *= (1.0f / 512.0f);
        float term = pooled * lin_w[a * 32 + lane];
#pragma unroll
        for (int off = 16; off > 0; off >>= 1)
            term += __shfl_xor_sync(0xffffffffu, term, off);
        if (lane == 0) s_delta[w] = 4.0f * tanhf(term + lin_b[a]);
    }

    float4 bias = reinterpret_cast<const float4*>(wp_b)[d0 >> 2];  // coalesced
    __syncthreads();  // s_wpT + s_delta ready

    // ---- weights smem -> regs: 16 conflict-free LDS.128 ----
    unsigned long long wp01[PPP], wp23[PPP];
#pragma unroll
    for (int p = 0; p < PPP; p++) {
        float4 wv = *reinterpret_cast<const float4*>(&s_wpT[p][d0]);
        wp01[p] = pack2(wv.x, wv.y);  // (w[d0][p],   w[d0+1][p])
        wp23[p] = pack2(wv.z, wv.w);  // (w[d0+2][p], w[d0+3][p])
    }
    const unsigned long long bb01 = pack2(bias.x, bias.y);
    const unsigned long long bb23 = pack2(bias.z, bias.w);

    // ---- bilinear sampling: thread owns (ai, p4-group, n) -> one STS.128 ----
    {
        const int nl = t & 31;
        const int n = h * 32 + nl;
        const int g = t >> 5;       // 0..7
        const int ai = g >> 2;      // 0..1
        const int p4 = g & 3;       // 0..3
        const float* xb = x + (size_t)b * LL * NNCH;
        const float base = (float)((a0 + ai) * 8) + s_delta[ai] - 7.5f;
        float vals[4];
#pragma unroll
        for (int j = 0; j < 4; j++) {
            int p = p4 * 4 + j;
            float xs = base + (float)p;
            xs = fminf(fmaxf(xs, 0.f), 511.f);
            float fl = floorf(xs);
            int i0 = (int)fl;
            float f = xs - fl;
            int i1 = min(i0 + 1, LL - 1);
            vals[j] = xb[i0 * NNCH + n] * (1.0f - f) + xb[i1 * NNCH + n] * f;
        }
        *reinterpret_cast<float4*>(&s_samp[ai][nl][p4 * 4]) =
            make_float4(vals[0], vals[1], vals[2], vals[3]);
    }
    __syncthreads();

    // ---- mainloop: 16 (row, anchor) combos per warp ----
#pragma unroll 1
    for (int c = 0; c < 16; c++) {
        const int ai = c >> 3;
        const int r = c & 7;
        const int row = q * 8 + r;
        const float* sp = &s_samp[ai][row][0];
        float4 sa = *reinterpret_cast<const float4*>(sp + 0);
        float4 sb = *reinterpret_cast<const float4*>(sp + 4);
        float4 sc = *reinterpret_cast<const float4*>(sp + 8);
        float4 sd = *reinterpret_cast<const float4*>(sp + 12);

        unsigned long long acc01 = bb01, acc23 = bb23;
#define PSTEP(sv, p)                      \
    {                                     \
        unsigned long long s2 = dup2(sv); \
        fma2(acc01, s2, wp01[p]);         \
        fma2(acc23, s2, wp23[p]);         \
    }
        PSTEP(sa.x, 0)
        PSTEP(sa.y, 1)
        PSTEP(sa.z, 2)
        PSTEP(sa.w, 3)
        PSTEP(sb.x, 4)
        PSTEP(sb.y, 5)
        PSTEP(sb.z, 6)
        PSTEP(sb.w, 7)
        PSTEP(sc.x, 8)
        PSTEP(sc.y, 9)
        PSTEP(sc.z, 10)
        PSTEP(sc.w, 11)
        PSTEP(sd.x, 12)
        PSTEP(sd.y, 13)
        PSTEP(sd.z, 14)
        PSTEP(sd.w, 15)
#undef PSTEP

        const int n = h * 32 + row;
        float* op =
            out + (((size_t)(b * 64 + n) * 64 + (a0 + ai)) * 256) + d0;
        float2 l0 = as_f2(acc01), l1 = as_f2(acc23);
        __stcs(reinterpret_cast<float4*>(op),
               make_float4(l0.x, l0.y, l1.x, l1.y));
    }
}

// ============================================================================
extern "C" void kernel_launch(void* const* d_in, const int* in_sizes, int n_in,
                              void* d_out, int out_size) {
    const float* x = (const float*)d_in[0];
    const float* conv_w = (const float*)d_in[1];
    const float* conv_b = (const float*)d_in[2];
    const float* lin_w = (const float*)d_in[3];
    const float* lin_b = (const float*)d_in[4];
    const float* wp_w = (const float*)d_in[5];
    const float* wp_b = (const float*)d_in[6];

    conv_pool_kernel<<<dim3(8, BB), 256>>>(x, conv_w, conv_b);
    patch_kernel<<<dim3(AAA / 2, BB, 2), 256>>>(x, lin_w, lin_b, wp_w, wp_b,
                                                (float*)d_out);
}